// round 16
// baseline (speedup 1.0000x reference)
#include <cuda_runtime.h>
#include <cuda_bf16.h>
#include <math.h>
#include <stdint.h>

#define IN_DIM 256
#define HID    128
#define NTOT   256          // concat output cols: [y(128) | r(128)]
#define MAXN   100000
#define MAXE   600000
#define SCAN_B 1024
#define MTILE  64           // rows per block (2 blocks/SM)

// ---- scratch (static device globals; no allocations allowed) ----
__device__ __align__(16) float g_yr[(size_t)MAXN * NTOT];   // [y | r] per node
__device__ __align__(16) float g_v[IN_DIM];                 // rp_w.T @ sh_w
__device__ float g_c0;
__device__ int   g_is64;
__device__ int g_cnt[MAXN];
__device__ int g_rowptr[MAXN + 1];
__device__ int g_cursor[MAXN];
__device__ int g_srclist[MAXE];
__device__ int g_bsum[(MAXN + SCAN_B - 1) / SCAN_B + 1];
// pre-swizzled bf16 W smem images: per chunk c: [Wh 32KB | Wl 32KB]
__device__ __align__(16) char g_wimg[4 * 65536];

// ---------------------------------------------------------------- helpers
__device__ __forceinline__ uint32_t smem_u32(const void* p) {
    uint32_t a;
    asm("{ .reg .u64 t; cvta.to.shared.u64 t, %1; cvt.u32.u64 %0, t; }"
        : "=r"(a) : "l"(p));
    return a;
}
__device__ __forceinline__ void ldsm4(uint32_t* r, uint32_t addr) {
    asm volatile("ldmatrix.sync.aligned.m8n8.x4.shared.b16 {%0,%1,%2,%3}, [%4];"
                 : "=r"(r[0]), "=r"(r[1]), "=r"(r[2]), "=r"(r[3]) : "r"(addr));
}
__device__ __forceinline__ void mma16816(float* c, const uint32_t* a,
                                         const uint32_t* b) {
    asm volatile("mma.sync.aligned.m16n8k16.row.col.f32.bf16.bf16.f32 "
                 "{%0,%1,%2,%3}, {%4,%5,%6,%7}, {%8,%9}, {%0,%1,%2,%3};"
                 : "+f"(c[0]), "+f"(c[1]), "+f"(c[2]), "+f"(c[3])
                 : "r"(a[0]), "r"(a[1]), "r"(a[2]), "r"(a[3]),
                   "r"(b[0]), "r"(b[1]));
}
__device__ __forceinline__ void cpa16(uint32_t dst, const void* src) {
    asm volatile("cp.async.cg.shared.global [%0], [%1], 16;"
                 :: "r"(dst), "l"(src) : "memory");
}
__device__ __forceinline__ void cpa_commit() {
    asm volatile("cp.async.commit_group;" ::: "memory");
}
__device__ __forceinline__ void cpa_wait0() {
    asm volatile("cp.async.wait_group 0;" ::: "memory");
}
#define SWZ(o) ((o) ^ (((o) >> 3) & 0x70))

__device__ __forceinline__ int load_idx(const int* ei, size_t pos) {
    if (g_is64) return (int)reinterpret_cast<const long long*>(ei)[pos];
    return ei[pos];
}

// rn-based split (W image)
__device__ __forceinline__ void cvt_hilo(float4 f, uint2& hv, uint2& lv) {
    __nv_bfloat16 h0 = __float2bfloat16_rn(f.x), h1 = __float2bfloat16_rn(f.y),
                  h2 = __float2bfloat16_rn(f.z), h3 = __float2bfloat16_rn(f.w);
    __nv_bfloat16 e0 = __float2bfloat16_rn(f.x - __bfloat162float(h0));
    __nv_bfloat16 e1 = __float2bfloat16_rn(f.y - __bfloat162float(h1));
    __nv_bfloat16 e2 = __float2bfloat16_rn(f.z - __bfloat162float(h2));
    __nv_bfloat16 e3 = __float2bfloat16_rn(f.w - __bfloat162float(h3));
    hv.x = ((uint32_t)__bfloat16_as_ushort(h1) << 16) | __bfloat16_as_ushort(h0);
    hv.y = ((uint32_t)__bfloat16_as_ushort(h3) << 16) | __bfloat16_as_ushort(h2);
    lv.x = ((uint32_t)__bfloat16_as_ushort(e1) << 16) | __bfloat16_as_ushort(e0);
    lv.y = ((uint32_t)__bfloat16_as_ushort(e3) << 16) | __bfloat16_as_ushort(e2);
}

// trunc-based split (X path)
__device__ __forceinline__ void cvt_trunc(float4 f, uint2& hv, uint2& lv) {
    uint32_t u0 = __float_as_uint(f.x), u1 = __float_as_uint(f.y);
    uint32_t u2 = __float_as_uint(f.z), u3 = __float_as_uint(f.w);
    hv.x = __byte_perm(u0, u1, 0x7632);
    hv.y = __byte_perm(u2, u3, 0x7632);
    float e0 = f.x - __uint_as_float(u0 & 0xFFFF0000u);
    float e1 = f.y - __uint_as_float(u1 & 0xFFFF0000u);
    float e2 = f.z - __uint_as_float(u2 & 0xFFFF0000u);
    float e3 = f.w - __uint_as_float(u3 & 0xFFFF0000u);
    asm("cvt.rn.bf16x2.f32 %0, %1, %2;" : "=r"(lv.x) : "f"(e1), "f"(e0));
    asm("cvt.rn.bf16x2.f32 %0, %1, %2;" : "=r"(lv.y) : "f"(e3), "f"(e2));
}

// ---------------------------------------------------------------- setup
__global__ void setup_kernel(const unsigned* __restrict__ ei32,
                             const float* __restrict__ rp_w,
                             const float* __restrict__ rp_b,
                             const float* __restrict__ sh_w,
                             const float* __restrict__ sh_b, int N) {
    int i = blockIdx.x * blockDim.x + threadIdx.x;
    if (i < N) g_cnt[i] = 0;
    if (blockIdx.x == 0) {
        int k = threadIdx.x;  // 256 threads
        if (k < 32) {
            int any = 0;
            for (int j = k; j < 64; j += 32)
                if (ei32[2 * j + 1] != 0u) any = 1;
            any = __any_sync(0xffffffffu, any);
            if (k == 0) g_is64 = !any;
        }
        float s = 0.f;
        for (int h = 0; h < HID; ++h) s += rp_w[h * IN_DIM + k] * sh_w[h];
        g_v[k] = s;
        if (k == 0) {
            float c = sh_b[0];
            for (int h = 0; h < HID; ++h) c += rp_b[h] * sh_w[h];
            g_c0 = c;
        }
    }
}

// ---------------------------------------------------------------- W image
__global__ void wconv_kernel(const float* __restrict__ wl,
                             const float* __restrict__ wr) {
    int t = blockIdx.x * blockDim.x + threadIdx.x;
    int c = t >> 12, l = t & 4095;
    int row = l >> 4, qf = l & 15;
    const float* srcp = (row < HID) ? (wl + (size_t)row * IN_DIM)
                                    : (wr + (size_t)(row - HID) * IN_DIM);
    float4 f = *(const float4*)(srcp + c * 64 + qf * 4);
    uint2 hv, lv;
    cvt_hilo(f, hv, lv);
    uint32_t off = SWZ((uint32_t)(row * 128 + qf * 8));
    *(uint2*)(g_wimg + c * 65536 + off) = hv;
    *(uint2*)(g_wimg + c * 65536 + 32768 + off) = lv;
}

// ---------------------------------------------------------------- CSR build
__global__ void hist_kernel(const int* __restrict__ ei, int E, int N) {
    int e = blockIdx.x * blockDim.x + threadIdx.x;
    if (e >= E) return;
    int dst = load_idx(ei, (size_t)E + e);
    dst = min(max(dst, 0), N - 1);
    atomicAdd(&g_cnt[dst], 1);
}
__global__ void scanA_kernel(int N) {
    __shared__ int s[SCAN_B];
    int tid = threadIdx.x;
    int i = blockIdx.x * SCAN_B + tid;
    int v = (i < N) ? g_cnt[i] : 0;
    s[tid] = v;
    __syncthreads();
    for (int off = 1; off < SCAN_B; off <<= 1) {
        int t = (tid >= off) ? s[tid - off] : 0;
        __syncthreads();
        s[tid] += t;
        __syncthreads();
    }
    if (i < N) g_rowptr[i] = s[tid] - v;
    if (tid == SCAN_B - 1) g_bsum[blockIdx.x] = s[tid];
}
__global__ void scanB_kernel(int nb) {
    __shared__ int s[SCAN_B];
    int tid = threadIdx.x;
    int v = (tid < nb) ? g_bsum[tid] : 0;
    s[tid] = v;
    __syncthreads();
    for (int off = 1; off < SCAN_B; off <<= 1) {
        int t = (tid >= off) ? s[tid - off] : 0;
        __syncthreads();
        s[tid] += t;
        __syncthreads();
    }
    if (tid < nb) g_bsum[tid] = s[tid] - v;
}
__global__ void scanC_kernel(int N, int E) {
    int i = blockIdx.x * blockDim.x + threadIdx.x;
    if (i < N) {
        int r = g_rowptr[i] + g_bsum[i / SCAN_B];
        g_rowptr[i] = r;
        g_cursor[i] = r;
    }
    if (i == 0) g_rowptr[N] = E;
}
__global__ void scatter_kernel(const int* __restrict__ ei, int E, int N) {
    int e = blockIdx.x * blockDim.x + threadIdx.x;
    if (e >= E) return;
    int src = load_idx(ei, e);
    int dst = load_idx(ei, (size_t)E + e);
    src = min(max(src, 0), N - 1);
    dst = min(max(dst, 0), N - 1);
    int pos = atomicAdd(&g_cursor[dst], 1);
    if (pos < MAXE) g_srclist[pos] = src;
}

// ---------------------------------------------------------------- HMMA GEMM
// D[64 x 256] = X[64 x 256] @ [lin_l ; lin_r]^T  (bf16 split x3, fp32 acc)
// 64-row tile, 2 blocks/SM (launch_bounds(256,2) caps regs at 128).
// Warp grid 2m x 4n, warp tile 32x64; acc[2][8][4]=64 regs.
// smem/block: Xh 8K | Xl 8K | W 64K (single buffer, cp.async at chunk top;
// cross-block occupancy hides the copy).
__global__ __launch_bounds__(256, 2)
void mma_kernel(const float* __restrict__ x,
                const float* __restrict__ rr,
                const float* __restrict__ alpha,
                float* __restrict__ out, int N) {
    extern __shared__ char dsm[];
    uint32_t sb   = smem_u32(dsm);
    uint32_t base = (sb + 127) & ~127u;
    char*    db   = dsm + (base - sb);
    uint32_t sXh = base, sXl = base + 8192;
    uint32_t sW  = base + 16384;           // 64KB single buffer
    char *pXh = db, *pXl = db + 8192;

    int tid = threadIdx.x, wid = tid >> 5, lane = tid & 31;
    int wm = wid & 1, wn = wid >> 1;       // 2m x 4n
    int m0 = blockIdx.x * MTILE;

    int aRow = (lane & 7) + ((lane >> 3) & 1) * 8;
    int aK   = ((lane >> 4) & 1) * 8;
    int bRow = (lane & 7) + ((lane >> 4) & 1) * 8;
    int bK   = ((lane >> 3) & 1) * 8;

    float acc[2][8][4];
    #pragma unroll
    for (int i = 0; i < 2; ++i)
        #pragma unroll
        for (int j = 0; j < 8; ++j)
            #pragma unroll
            for (int q = 0; q < 4; ++q) acc[i][j][q] = 0.f;

    const int qf = tid & 15;
    const int rbase = tid >> 4;            // 0..15; rows rbase + 16*i, i<4
    float dp[4];
    #pragma unroll
    for (int i = 0; i < 4; ++i) dp[i] = 0.f;

    // preload X chunk 0 into registers
    float4 px[4];
    #pragma unroll
    for (int i = 0; i < 4; ++i) {
        int grow = min(m0 + rbase + 16 * i, N - 1);
        px[i] = *(const float4*)(x + (size_t)grow * IN_DIM + qf * 4);
    }

    for (int c = 0; c < 4; ++c) {
        if (c) __syncthreads();   // mma(c-1) done reading sX/sW
        // ---- issue W(c) copy (overlaps convert below; other block's MMA
        //      hides residual latency via 2-block occupancy)
        {
            const char* wsrc = g_wimg + c * 65536;
            #pragma unroll
            for (int i = 0; i < 16; ++i) {
                int t = (tid + i * 256) * 16;
                cpa16(sW + t, wsrc + t);
            }
            cpa_commit();
        }
        float4 vv = *(const float4*)(g_v + c * 64 + qf * 4);
        // ---- convert preloaded X chunk -> smem; accumulate dot partials
        #pragma unroll
        for (int i = 0; i < 4; ++i) {
            int row = rbase + i * 16;
            float4 f = px[i];
            dp[i] += f.x * vv.x + f.y * vv.y + f.z * vv.z + f.w * vv.w;
            uint2 hv, lv;
            cvt_trunc(f, hv, lv);
            uint32_t off = SWZ((uint32_t)(row * 128 + qf * 8));
            *(uint2*)(pXh + off) = hv;
            *(uint2*)(pXl + off) = lv;
        }
        // ---- preload next X chunk (completes during MMA)
        if (c < 3) {
            #pragma unroll
            for (int i = 0; i < 4; ++i) {
                int grow = min(m0 + rbase + 16 * i, N - 1);
                px[i] = *(const float4*)(x + (size_t)grow * IN_DIM
                                         + (c + 1) * 64 + qf * 4);
            }
        }
        cpa_wait0();
        __syncthreads();

        uint32_t sWh = sW;
        uint32_t sWl = sW + 32768;
        #pragma unroll
        for (int k16 = 0; k16 < 4; ++k16) {
            int k0 = k16 * 16;
            uint32_t ah[2][4], al[2][4];
            #pragma unroll
            for (int mf = 0; mf < 2; ++mf) {
                uint32_t off = SWZ((uint32_t)((wm * 32 + mf * 16 + aRow) * 128
                                              + (k0 + aK) * 2));
                ldsm4(ah[mf], sXh + off);
                ldsm4(al[mf], sXl + off);
            }
            #pragma unroll
            for (int nf2 = 0; nf2 < 4; ++nf2) {
                uint32_t offB = SWZ((uint32_t)((wn * 64 + nf2 * 16 + bRow) * 128
                                               + (k0 + bK) * 2));
                uint32_t bh[4], bl[4];
                ldsm4(bh, sWh + offB);
                ldsm4(bl, sWl + offB);
                #pragma unroll
                for (int mf = 0; mf < 2; ++mf) {
                    mma16816(acc[mf][2 * nf2],     ah[mf], bh);
                    mma16816(acc[mf][2 * nf2 + 1], ah[mf], bh + 2);
                    mma16816(acc[mf][2 * nf2],     ah[mf], bl);
                    mma16816(acc[mf][2 * nf2 + 1], ah[mf], bl + 2);
                    mma16816(acc[mf][2 * nf2],     al[mf], bh);
                    mma16816(acc[mf][2 * nf2 + 1], al[mf], bh + 2);
                }
            }
        }
    }

    // fused base epilogue: one reduce per row, single-writer store
    {
        float av = 1.f / (1.f + expf(-alpha[0]));
        #pragma unroll
        for (int i = 0; i < 4; ++i) {
            float d = dp[i];
            #pragma unroll
            for (int o = 1; o < 16; o <<= 1)
                d += __shfl_xor_sync(0xffffffffu, d, o);
            if (qf == 0) {
                int node = m0 + rbase + 16 * i;
                if (node < N)
                    out[node] = av * rr[node] + (1.f - av) * (d + g_c0);
            }
        }
    }

    // GEMM epilogue: write g_yr
    int grp = lane >> 2, qd = lane & 3;
    #pragma unroll
    for (int mf = 0; mf < 2; ++mf) {
        int r0 = m0 + wm * 32 + mf * 16 + grp;
        int r1 = r0 + 8;
        #pragma unroll
        for (int nf = 0; nf < 8; ++nf) {
            int col = wn * 64 + nf * 8 + qd * 2;
            if (r0 < N) {
                float2 v0 = make_float2(acc[mf][nf][0], acc[mf][nf][1]);
                *(float2*)(g_yr + (size_t)r0 * NTOT + col) = v0;
            }
            if (r1 < N) {
                float2 v1 = make_float2(acc[mf][nf][2], acc[mf][nf][3]);
                *(float2*)(g_yr + (size_t)r1 * NTOT + col) = v1;
            }
        }
    }
}

// ---------------------------------------------------------------- gather + epilogue
// one warp per dst node; 4-deep index prefetch for MLP; __ldg reads
__global__ void gather_kernel(const float* __restrict__ lin_l_b,
                              const float* __restrict__ sh_w,
                              const float* __restrict__ alpha,
                              float* __restrict__ out, int N) {
    int node = blockIdx.x * 8 + (threadIdx.x >> 5);
    int lane = threadIdx.x & 31;
    if (node >= N) return;
    float4 b4 = reinterpret_cast<const float4*>(lin_l_b)[lane];
    float4 s4 = reinterpret_cast<const float4*>(sh_w)[lane];
    int s0 = __ldg(&g_rowptr[node]);
    int s1 = __ldg(&g_rowptr[node + 1]);
    float4 acc = make_float4(0.f, 0.f, 0.f, 0.f);
    int e = s0;
    for (; e + 3 < s1; e += 4) {
        int i0 = __ldg(&g_srclist[e]);
        int i1 = __ldg(&g_srclist[e + 1]);
        int i2 = __ldg(&g_srclist[e + 2]);
        int i3 = __ldg(&g_srclist[e + 3]);
        float4 v0 = __ldg(reinterpret_cast<const float4*>(g_yr + (size_t)i0 * NTOT) + lane);
        float4 v1 = __ldg(reinterpret_cast<const float4*>(g_yr + (size_t)i1 * NTOT) + lane);
        float4 v2 = __ldg(reinterpret_cast<const float4*>(g_yr + (size_t)i2 * NTOT) + lane);
        float4 v3 = __ldg(reinterpret_cast<const float4*>(g_yr + (size_t)i3 * NTOT) + lane);
        acc.x += (v0.x + v1.x) + (v2.x + v3.x);
        acc.y += (v0.y + v1.y) + (v2.y + v3.y);
        acc.z += (v0.z + v1.z) + (v2.z + v3.z);
        acc.w += (v0.w + v1.w) + (v2.w + v3.w);
    }
    for (; e < s1; ++e) {
        int i0 = __ldg(&g_srclist[e]);
        float4 v0 = __ldg(reinterpret_cast<const float4*>(g_yr + (size_t)i0 * NTOT) + lane);
        acc.x += v0.x; acc.y += v0.y; acc.z += v0.z; acc.w += v0.w;
    }
    float inv = 1.f / fmaxf((float)(s1 - s0), 1.f);
    float4 r4 = __ldg(reinterpret_cast<const float4*>(g_yr + (size_t)node * NTOT + HID) + lane);
    float part = fmaxf(acc.x * inv + b4.x + r4.x, 0.f) * s4.x
               + fmaxf(acc.y * inv + b4.y + r4.y, 0.f) * s4.y
               + fmaxf(acc.z * inv + b4.z + r4.z, 0.f) * s4.z
               + fmaxf(acc.w * inv + b4.w + r4.w, 0.f) * s4.w;
    #pragma unroll
    for (int o = 16; o; o >>= 1) part += __shfl_xor_sync(0xffffffffu, part, o);
    if (lane == 0) {
        float av = 1.f / (1.f + expf(-alpha[0]));
        out[node] += (1.f - av) * part;
    }
}

// ============================================================================
extern "C" void kernel_launch(void* const* d_in, const int* in_sizes, int n_in,
                              void* d_out, int out_size) {
    const float* x        = (const float*)d_in[0];
    const int*   ei       = (const int*)d_in[1];
    const float* rr       = (const float*)d_in[2];
    const float* lin_l_w  = (const float*)d_in[3];
    const float* lin_l_b  = (const float*)d_in[4];
    const float* lin_r_w  = (const float*)d_in[5];
    const float* rp_w     = (const float*)d_in[6];
    const float* rp_b     = (const float*)d_in[7];
    const float* sh_w     = (const float*)d_in[8];
    const float* sh_b     = (const float*)d_in[9];
    const float* alpha    = (const float*)d_in[10];
    float* out = (float*)d_out;

    int N = in_sizes[2];
    int E = in_sizes[1] / 2;
    if (E > MAXE) E = MAXE;
    int nblkN = (N + SCAN_B - 1) / SCAN_B;
    int smem = 81920 + 128;

    cudaFuncSetAttribute(mma_kernel,
                         cudaFuncAttributeMaxDynamicSharedMemorySize, smem);

    // fork a side stream for the CSR build (capture-safe via event edges)
    cudaStream_t s2;
    cudaStreamCreateWithFlags(&s2, cudaStreamNonBlocking);
    cudaEvent_t evRoot, evSetup, evCSR;
    cudaEventCreateWithFlags(&evRoot, cudaEventDisableTiming);
    cudaEventCreateWithFlags(&evSetup, cudaEventDisableTiming);
    cudaEventCreateWithFlags(&evCSR, cudaEventDisableTiming);

    cudaEventRecord(evRoot, 0);
    cudaStreamWaitEvent(s2, evRoot, 0);

    // mma_kernel kept at launch #4 so ncu's window profiles it.
    // #1 (s2): setup
    setup_kernel<<<(N + 255) / 256, 256, 0, s2>>>((const unsigned*)ei, rp_w,
                                                  rp_b, sh_w, sh_b, N);
    cudaEventRecord(evSetup, s2);
    // #2 (main): W image
    wconv_kernel<<<64, 256>>>(lin_l_w, lin_r_w);
    // #3 (s2): hist
    hist_kernel<<<(E + 255) / 256, 256, 0, s2>>>(ei, E, N);
    // #4 (main): the GEMM — profiled launch
    cudaStreamWaitEvent(0, evSetup, 0);
    mma_kernel<<<(N + MTILE - 1) / MTILE, 256, smem>>>(x, rr, alpha, out, N);
    // #5..#8 (s2): rest of CSR chain (runs concurrent with mma)
    scanA_kernel<<<nblkN, SCAN_B, 0, s2>>>(N);
    scanB_kernel<<<1, SCAN_B, 0, s2>>>(nblkN);
    scanC_kernel<<<(N + 255) / 256, 256, 0, s2>>>(N, E);
    scatter_kernel<<<(E + 255) / 256, 256, 0, s2>>>(ei, E, N);
    cudaEventRecord(evCSR, s2);
    // #9 (main): gather after both mma (stream order) and CSR (event)
    cudaStreamWaitEvent(0, evCSR, 0);
    gather_kernel<<<(N + 7) / 8, 256>>>(lin_l_b, sh_w, alpha, out, N);
}

// round 17
// speedup vs baseline: 1.1889x; 1.1889x over previous
#include <cuda_runtime.h>
#include <cuda_fp16.h>
#include <math.h>
#include <stdint.h>

#define IN_DIM 256
#define HID    128
#define NTOT   256          // concat output cols: [y(128) | r(128)]
#define MAXN   100000
#define MAXE   600000
#define SCAN_B 1024
#define MTILE  64           // rows per block (2 blocks/SM)

// ---- scratch (static device globals; no allocations allowed) ----
__device__ __align__(16) float g_yr[(size_t)MAXN * NTOT];   // [y | r] per node
__device__ __align__(16) float g_v[IN_DIM];                 // rp_w.T @ sh_w
__device__ float g_c0;
__device__ int   g_is64;
__device__ int g_cnt[MAXN];
__device__ int g_rowptr[MAXN + 1];
__device__ int g_cursor[MAXN];
__device__ int g_srclist[MAXE];
__device__ int g_bsum[(MAXN + SCAN_B - 1) / SCAN_B + 1];
// pre-swizzled fp16 W smem images: per chunk c: [Wh 32KB | Wl 32KB]
__device__ __align__(16) char g_wimg[4 * 65536];

// ---------------------------------------------------------------- helpers
__device__ __forceinline__ uint32_t smem_u32(const void* p) {
    uint32_t a;
    asm("{ .reg .u64 t; cvta.to.shared.u64 t, %1; cvt.u32.u64 %0, t; }"
        : "=r"(a) : "l"(p));
    return a;
}
__device__ __forceinline__ void ldsm4(uint32_t* r, uint32_t addr) {
    asm volatile("ldmatrix.sync.aligned.m8n8.x4.shared.b16 {%0,%1,%2,%3}, [%4];"
                 : "=r"(r[0]), "=r"(r[1]), "=r"(r[2]), "=r"(r[3]) : "r"(addr));
}
__device__ __forceinline__ void mma16816(float* c, const uint32_t* a,
                                         const uint32_t* b) {
    asm volatile("mma.sync.aligned.m16n8k16.row.col.f32.f16.f16.f32 "
                 "{%0,%1,%2,%3}, {%4,%5,%6,%7}, {%8,%9}, {%0,%1,%2,%3};"
                 : "+f"(c[0]), "+f"(c[1]), "+f"(c[2]), "+f"(c[3])
                 : "r"(a[0]), "r"(a[1]), "r"(a[2]), "r"(a[3]),
                   "r"(b[0]), "r"(b[1]));
}
__device__ __forceinline__ void cpa16(uint32_t dst, const void* src) {
    asm volatile("cp.async.cg.shared.global [%0], [%1], 16;"
                 :: "r"(dst), "l"(src) : "memory");
}
__device__ __forceinline__ void cpa_commit() {
    asm volatile("cp.async.commit_group;" ::: "memory");
}
__device__ __forceinline__ void cpa_wait0() {
    asm volatile("cp.async.wait_group 0;" ::: "memory");
}
#define SWZ(o) ((o) ^ (((o) >> 3) & 0x70))

__device__ __forceinline__ int load_idx(const int* ei, size_t pos) {
    if (g_is64) return (int)reinterpret_cast<const long long*>(ei)[pos];
    return ei[pos];
}

// fp16 hi/lo split (W image): wh = fp16(w), wl = fp16(w - wh)
__device__ __forceinline__ void cvt_hilo_f16(float4 f, uint2& hv, uint2& lv) {
    __half h0 = __float2half_rn(f.x), h1 = __float2half_rn(f.y),
           h2 = __float2half_rn(f.z), h3 = __float2half_rn(f.w);
    __half e0 = __float2half_rn(f.x - __half2float(h0));
    __half e1 = __float2half_rn(f.y - __half2float(h1));
    __half e2 = __float2half_rn(f.z - __half2float(h2));
    __half e3 = __float2half_rn(f.w - __half2float(h3));
    hv.x = ((uint32_t)__half_as_ushort(h1) << 16) | __half_as_ushort(h0);
    hv.y = ((uint32_t)__half_as_ushort(h3) << 16) | __half_as_ushort(h2);
    lv.x = ((uint32_t)__half_as_ushort(e1) << 16) | __half_as_ushort(e0);
    lv.y = ((uint32_t)__half_as_ushort(e3) << 16) | __half_as_ushort(e2);
}

// ---------------------------------------------------------------- setup
__global__ void setup_kernel(const unsigned* __restrict__ ei32,
                             const float* __restrict__ rp_w,
                             const float* __restrict__ rp_b,
                             const float* __restrict__ sh_w,
                             const float* __restrict__ sh_b, int N) {
    int i = blockIdx.x * blockDim.x + threadIdx.x;
    if (i < N) g_cnt[i] = 0;
    if (blockIdx.x == 0) {
        int k = threadIdx.x;  // 256 threads
        if (k < 32) {
            int any = 0;
            for (int j = k; j < 64; j += 32)
                if (ei32[2 * j + 1] != 0u) any = 1;
            any = __any_sync(0xffffffffu, any);
            if (k == 0) g_is64 = !any;
        }
        float s = 0.f;
        for (int h = 0; h < HID; ++h) s += rp_w[h * IN_DIM + k] * sh_w[h];
        g_v[k] = s;
        if (k == 0) {
            float c = sh_b[0];
            for (int h = 0; h < HID; ++h) c += rp_b[h] * sh_w[h];
            g_c0 = c;
        }
    }
}

// ---------------------------------------------------------------- W image
__global__ void wconv_kernel(const float* __restrict__ wl,
                             const float* __restrict__ wr) {
    int t = blockIdx.x * blockDim.x + threadIdx.x;
    int c = t >> 12, l = t & 4095;
    int row = l >> 4, qf = l & 15;
    const float* srcp = (row < HID) ? (wl + (size_t)row * IN_DIM)
                                    : (wr + (size_t)(row - HID) * IN_DIM);
    float4 f = *(const float4*)(srcp + c * 64 + qf * 4);
    uint2 hv, lv;
    cvt_hilo_f16(f, hv, lv);
    uint32_t off = SWZ((uint32_t)(row * 128 + qf * 8));
    *(uint2*)(g_wimg + c * 65536 + off) = hv;
    *(uint2*)(g_wimg + c * 65536 + 32768 + off) = lv;
}

// ---------------------------------------------------------------- CSR build
__global__ void hist_kernel(const int* __restrict__ ei, int E, int N) {
    int e = blockIdx.x * blockDim.x + threadIdx.x;
    if (e >= E) return;
    int dst = load_idx(ei, (size_t)E + e);
    dst = min(max(dst, 0), N - 1);
    atomicAdd(&g_cnt[dst], 1);
}
__global__ void scanA_kernel(int N) {
    __shared__ int s[SCAN_B];
    int tid = threadIdx.x;
    int i = blockIdx.x * SCAN_B + tid;
    int v = (i < N) ? g_cnt[i] : 0;
    s[tid] = v;
    __syncthreads();
    for (int off = 1; off < SCAN_B; off <<= 1) {
        int t = (tid >= off) ? s[tid - off] : 0;
        __syncthreads();
        s[tid] += t;
        __syncthreads();
    }
    if (i < N) g_rowptr[i] = s[tid] - v;
    if (tid == SCAN_B - 1) g_bsum[blockIdx.x] = s[tid];
}
__global__ void scanB_kernel(int nb) {
    __shared__ int s[SCAN_B];
    int tid = threadIdx.x;
    int v = (tid < nb) ? g_bsum[tid] : 0;
    s[tid] = v;
    __syncthreads();
    for (int off = 1; off < SCAN_B; off <<= 1) {
        int t = (tid >= off) ? s[tid - off] : 0;
        __syncthreads();
        s[tid] += t;
        __syncthreads();
    }
    if (tid < nb) g_bsum[tid] = s[tid] - v;
}
__global__ void scanC_kernel(int N, int E) {
    int i = blockIdx.x * blockDim.x + threadIdx.x;
    if (i < N) {
        int r = g_rowptr[i] + g_bsum[i / SCAN_B];
        g_rowptr[i] = r;
        g_cursor[i] = r;
    }
    if (i == 0) g_rowptr[N] = E;
}
__global__ void scatter_kernel(const int* __restrict__ ei, int E, int N) {
    int e = blockIdx.x * blockDim.x + threadIdx.x;
    if (e >= E) return;
    int src = load_idx(ei, e);
    int dst = load_idx(ei, (size_t)E + e);
    src = min(max(src, 0), N - 1);
    dst = min(max(dst, 0), N - 1);
    int pos = atomicAdd(&g_cursor[dst], 1);
    if (pos < MAXE) g_srclist[pos] = src;
}

// ---------------------------------------------------------------- HMMA GEMM
// D[64 x 256] = X[64 x 256] @ [lin_l ; lin_r]^T
// fp16 2-term split: D = Xh*Wh + Xh*Wl  (X residual 2^-12 dropped).
// 64-row tile, 2 blocks/SM. Warp grid 2m x 4n, warp tile 32x64.
// smem/block: Xh 8K | W 64K (cp.async at chunk top).
__global__ __launch_bounds__(256, 2)
void mma_kernel(const float* __restrict__ x,
                const float* __restrict__ rr,
                const float* __restrict__ alpha,
                float* __restrict__ out, int N) {
    extern __shared__ char dsm[];
    uint32_t sb   = smem_u32(dsm);
    uint32_t base = (sb + 127) & ~127u;
    char*    db   = dsm + (base - sb);
    uint32_t sXh = base;
    uint32_t sW  = base + 8192;            // 64KB single buffer
    char *pXh = db;

    int tid = threadIdx.x, wid = tid >> 5, lane = tid & 31;
    int wm = wid & 1, wn = wid >> 1;       // 2m x 4n
    int m0 = blockIdx.x * MTILE;

    int aRow = (lane & 7) + ((lane >> 3) & 1) * 8;
    int aK   = ((lane >> 4) & 1) * 8;
    int bRow = (lane & 7) + ((lane >> 4) & 1) * 8;
    int bK   = ((lane >> 3) & 1) * 8;

    float acc[2][8][4];
    #pragma unroll
    for (int i = 0; i < 2; ++i)
        #pragma unroll
        for (int j = 0; j < 8; ++j)
            #pragma unroll
            for (int q = 0; q < 4; ++q) acc[i][j][q] = 0.f;

    const int qf = tid & 15;
    const int rbase = tid >> 4;            // 0..15; rows rbase + 16*i, i<4
    float dp[4];
    #pragma unroll
    for (int i = 0; i < 4; ++i) dp[i] = 0.f;

    // preload X chunk 0 into registers
    float4 px[4];
    #pragma unroll
    for (int i = 0; i < 4; ++i) {
        int grow = min(m0 + rbase + 16 * i, N - 1);
        px[i] = *(const float4*)(x + (size_t)grow * IN_DIM + qf * 4);
    }

    for (int c = 0; c < 4; ++c) {
        if (c) __syncthreads();   // mma(c-1) done reading sX/sW
        // ---- issue W(c) copy (overlaps convert; peer block's MMA hides rest)
        {
            const char* wsrc = g_wimg + c * 65536;
            #pragma unroll
            for (int i = 0; i < 16; ++i) {
                int t = (tid + i * 256) * 16;
                cpa16(sW + t, wsrc + t);
            }
            cpa_commit();
        }
        float4 vv = *(const float4*)(g_v + c * 64 + qf * 4);
        // ---- convert preloaded X chunk -> fp16 smem; accumulate dot partials
        #pragma unroll
        for (int i = 0; i < 4; ++i) {
            int row = rbase + i * 16;
            float4 f = px[i];
            dp[i] += f.x * vv.x + f.y * vv.y + f.z * vv.z + f.w * vv.w;
            uint2 hv;
            asm("cvt.rn.f16x2.f32 %0, %1, %2;" : "=r"(hv.x) : "f"(f.y), "f"(f.x));
            asm("cvt.rn.f16x2.f32 %0, %1, %2;" : "=r"(hv.y) : "f"(f.w), "f"(f.z));
            uint32_t off = SWZ((uint32_t)(row * 128 + qf * 8));
            *(uint2*)(pXh + off) = hv;
        }
        // ---- preload next X chunk (completes during MMA)
        if (c < 3) {
            #pragma unroll
            for (int i = 0; i < 4; ++i) {
                int grow = min(m0 + rbase + 16 * i, N - 1);
                px[i] = *(const float4*)(x + (size_t)grow * IN_DIM
                                         + (c + 1) * 64 + qf * 4);
            }
        }
        cpa_wait0();
        __syncthreads();

        uint32_t sWh = sW;
        uint32_t sWl = sW + 32768;
        #pragma unroll
        for (int k16 = 0; k16 < 4; ++k16) {
            int k0 = k16 * 16;
            uint32_t ah[2][4];
            #pragma unroll
            for (int mf = 0; mf < 2; ++mf) {
                uint32_t off = SWZ((uint32_t)((wm * 32 + mf * 16 + aRow) * 128
                                              + (k0 + aK) * 2));
                ldsm4(ah[mf], sXh + off);
            }
            #pragma unroll
            for (int nf2 = 0; nf2 < 4; ++nf2) {
                uint32_t offB = SWZ((uint32_t)((wn * 64 + nf2 * 16 + bRow) * 128
                                               + (k0 + bK) * 2));
                uint32_t bh[4], bl[4];
                ldsm4(bh, sWh + offB);
                ldsm4(bl, sWl + offB);
                #pragma unroll
                for (int mf = 0; mf < 2; ++mf) {
                    mma16816(acc[mf][2 * nf2],     ah[mf], bh);
                    mma16816(acc[mf][2 * nf2 + 1], ah[mf], bh + 2);
                    mma16816(acc[mf][2 * nf2],     ah[mf], bl);
                    mma16816(acc[mf][2 * nf2 + 1], ah[mf], bl + 2);
                }
            }
        }
    }

    // fused base epilogue: one reduce per row, single-writer store
    {
        float av = 1.f / (1.f + expf(-alpha[0]));
        #pragma unroll
        for (int i = 0; i < 4; ++i) {
            float d = dp[i];
            #pragma unroll
            for (int o = 1; o < 16; o <<= 1)
                d += __shfl_xor_sync(0xffffffffu, d, o);
            if (qf == 0) {
                int node = m0 + rbase + 16 * i;
                if (node < N)
                    out[node] = av * rr[node] + (1.f - av) * (d + g_c0);
            }
        }
    }

    // GEMM epilogue: write g_yr
    int grp = lane >> 2, qd = lane & 3;
    #pragma unroll
    for (int mf = 0; mf < 2; ++mf) {
        int r0 = m0 + wm * 32 + mf * 16 + grp;
        int r1 = r0 + 8;
        #pragma unroll
        for (int nf = 0; nf < 8; ++nf) {
            int col = wn * 64 + nf * 8 + qd * 2;
            if (r0 < N) {
                float2 v0 = make_float2(acc[mf][nf][0], acc[mf][nf][1]);
                *(float2*)(g_yr + (size_t)r0 * NTOT + col) = v0;
            }
            if (r1 < N) {
                float2 v1 = make_float2(acc[mf][nf][2], acc[mf][nf][3]);
                *(float2*)(g_yr + (size_t)r1 * NTOT + col) = v1;
            }
        }
    }
}

// ---------------------------------------------------------------- gather + epilogue
// one warp per dst node (round-13 form: 2-deep unroll, plain loads)
__global__ void gather_kernel(const float* __restrict__ lin_l_b,
                              const float* __restrict__ sh_w,
                              const float* __restrict__ alpha,
                              float* __restrict__ out, int N) {
    int node = blockIdx.x * 8 + (threadIdx.x >> 5);
    int lane = threadIdx.x & 31;
    if (node >= N) return;
    float4 b4 = reinterpret_cast<const float4*>(lin_l_b)[lane];
    float4 s4 = reinterpret_cast<const float4*>(sh_w)[lane];
    int s0 = g_rowptr[node], s1 = g_rowptr[node + 1];
    float4 acc = make_float4(0.f, 0.f, 0.f, 0.f);
    int e = s0;
    for (; e + 1 < s1; e += 2) {
        int sa = g_srclist[e], sb = g_srclist[e + 1];
        float4 va = reinterpret_cast<const float4*>(g_yr + (size_t)sa * NTOT)[lane];
        float4 vb = reinterpret_cast<const float4*>(g_yr + (size_t)sb * NTOT)[lane];
        acc.x += va.x + vb.x; acc.y += va.y + vb.y;
        acc.z += va.z + vb.z; acc.w += va.w + vb.w;
    }
    if (e < s1) {
        int sa = g_srclist[e];
        float4 va = reinterpret_cast<const float4*>(g_yr + (size_t)sa * NTOT)[lane];
        acc.x += va.x; acc.y += va.y; acc.z += va.z; acc.w += va.w;
    }
    float inv = 1.f / fmaxf((float)(s1 - s0), 1.f);
    float4 r4 = reinterpret_cast<const float4*>(g_yr + (size_t)node * NTOT + HID)[lane];
    float part = fmaxf(acc.x * inv + b4.x + r4.x, 0.f) * s4.x
               + fmaxf(acc.y * inv + b4.y + r4.y, 0.f) * s4.y
               + fmaxf(acc.z * inv + b4.z + r4.z, 0.f) * s4.z
               + fmaxf(acc.w * inv + b4.w + r4.w, 0.f) * s4.w;
    #pragma unroll
    for (int o = 16; o; o >>= 1) part += __shfl_xor_sync(0xffffffffu, part, o);
    if (lane == 0) {
        float av = 1.f / (1.f + expf(-alpha[0]));
        out[node] += (1.f - av) * part;
    }
}

// ============================================================================
extern "C" void kernel_launch(void* const* d_in, const int* in_sizes, int n_in,
                              void* d_out, int out_size) {
    const float* x        = (const float*)d_in[0];
    const int*   ei       = (const int*)d_in[1];
    const float* rr       = (const float*)d_in[2];
    const float* lin_l_w  = (const float*)d_in[3];
    const float* lin_l_b  = (const float*)d_in[4];
    const float* lin_r_w  = (const float*)d_in[5];
    const float* rp_w     = (const float*)d_in[6];
    const float* rp_b     = (const float*)d_in[7];
    const float* sh_w     = (const float*)d_in[8];
    const float* sh_b     = (const float*)d_in[9];
    const float* alpha    = (const float*)d_in[10];
    float* out = (float*)d_out;

    int N = in_sizes[2];
    int E = in_sizes[1] / 2;
    if (E > MAXE) E = MAXE;
    int nblkN = (N + SCAN_B - 1) / SCAN_B;
    int smem = 73728 + 128;

    cudaFuncSetAttribute(mma_kernel,
                         cudaFuncAttributeMaxDynamicSharedMemorySize, smem);

    // fork a side stream for the CSR build (capture-safe via event edges)
    cudaStream_t s2;
    cudaStreamCreateWithFlags(&s2, cudaStreamNonBlocking);
    cudaEvent_t evRoot, evSetup, evCSR;
    cudaEventCreateWithFlags(&evRoot, cudaEventDisableTiming);
    cudaEventCreateWithFlags(&evSetup, cudaEventDisableTiming);
    cudaEventCreateWithFlags(&evCSR, cudaEventDisableTiming);

    cudaEventRecord(evRoot, 0);
    cudaStreamWaitEvent(s2, evRoot, 0);

    // mma_kernel kept at launch #4 so ncu's window profiles it.
    // #1 (s2): setup
    setup_kernel<<<(N + 255) / 256, 256, 0, s2>>>((const unsigned*)ei, rp_w,
                                                  rp_b, sh_w, sh_b, N);
    cudaEventRecord(evSetup, s2);
    // #2 (main): W image
    wconv_kernel<<<64, 256>>>(lin_l_w, lin_r_w);
    // #3 (s2): hist
    hist_kernel<<<(E + 255) / 256, 256, 0, s2>>>(ei, E, N);
    // #4 (main): the GEMM — profiled launch
    cudaStreamWaitEvent(0, evSetup, 0);
    mma_kernel<<<(N + MTILE - 1) / MTILE, 256, smem>>>(x, rr, alpha, out, N);
    // #5..#8 (s2): rest of CSR chain (runs concurrent with mma)
    scanA_kernel<<<nblkN, SCAN_B, 0, s2>>>(N);
    scanB_kernel<<<1, SCAN_B, 0, s2>>>(nblkN);
    scanC_kernel<<<(N + 255) / 256, 256, 0, s2>>>(N, E);
    scatter_kernel<<<(E + 255) / 256, 256, 0, s2>>>(ei, E, N);
    cudaEventRecord(evCSR, s2);
    // #9 (main): gather after both mma (stream order) and CSR (event)
    cudaStreamWaitEvent(0, evCSR, 0);
    gather_kernel<<<(N + 7) / 8, 256>>>(lin_l_b, sh_w, alpha, out, N);
}